// round 10
// baseline (speedup 1.0000x reference)
#include <cuda_runtime.h>
#include <cuda_bf16.h>
#include <cuda_fp16.h>
#include <cuda_fp8.h>
#include <cstddef>

#define NN 50000
#define EE 800000
#define NF 256
#define HH 128
#define LL 3
#define NEG_SLOPE 0.01f
#define NBLK 196   // ceil(NN/256)

// ---------------- scratch (no allocations allowed) ----------------
__device__ float         g_cur[(size_t)NN * HH];   // current hidden h (fp32)
__device__ float         g_agg[(size_t)NN * HH];   // aggregation buffer (fp32)
__device__ unsigned char g_h08 [(size_t)NN * HH];  // projection output (fp8 e4m3)
__device__ unsigned char g_msg8[(size_t)NN * HH];  // h*invdeg messages (fp8 e4m3)
__device__ float g_invdeg[NN];
__device__ float g_colsum[HH * (LL + 1)];
__device__ int   g_cnt[NN];
__device__ int   g_rank[EE];
__device__ int   g_rowptr[NN + 1];
__device__ int   g_col[EE];                // src node per dst-sorted edge
__device__ int   g_bsum[NBLK];
__device__ int   g_boff[NBLK];

// ---------------- helpers ----------------
__device__ __forceinline__ unsigned f2tf32(float x) {
    unsigned u;
    asm("cvt.rna.tf32.f32 %0, %1;" : "=r"(u) : "f"(x));
    return u;
}

__device__ __forceinline__ void mma_tf32(float* d, const unsigned* a, const unsigned* b) {
    asm volatile(
        "mma.sync.aligned.m16n8k8.row.col.f32.tf32.tf32.f32 "
        "{%0,%1,%2,%3}, {%4,%5,%6,%7}, {%8,%9}, {%0,%1,%2,%3};\n"
        : "+f"(d[0]), "+f"(d[1]), "+f"(d[2]), "+f"(d[3])
        : "r"(a[0]), "r"(a[1]), "r"(a[2]), "r"(a[3]), "r"(b[0]), "r"(b[1]));
}

// encode two floats -> fp8x2 (e4m3, satfinite)
__device__ __forceinline__ unsigned short packfp8x2(float lo, float hi) {
    return (unsigned short)__nv_cvt_float2_to_fp8x2(make_float2(lo, hi),
                                                    __NV_SATFINITE, __NV_E4M3);
}

// accumulate 4 fp8 values (one 4-byte word) into float4
__device__ __forceinline__ void acc_fp8row(float4& acc, const unsigned char* p) {
    unsigned u = *reinterpret_cast<const unsigned*>(p);
    __half2_raw r0 = __nv_cvt_fp8x2_to_halfraw2((__nv_fp8x2_storage_t)(u & 0xffffu), __NV_E4M3);
    __half2_raw r1 = __nv_cvt_fp8x2_to_halfraw2((__nv_fp8x2_storage_t)(u >> 16), __NV_E4M3);
    float2 f0 = __half22float2(*reinterpret_cast<__half2*>(&r0));
    float2 f1 = __half22float2(*reinterpret_cast<__half2*>(&r1));
    acc.x += f0.x; acc.y += f0.y; acc.z += f1.x; acc.w += f1.y;
}

// ---------------- colsum zero (main stream, before fork) ----------------
__global__ void zero_cs_kernel(float* __restrict__ cs) {
    int i = blockIdx.x * blockDim.x + threadIdx.x;
    if (i < HH * (LL + 1)) cs[i] = 0.f;
}

// ---------------- init (s2): counters + invdeg ----------------
__global__ void init_kernel(const float* __restrict__ degree, float* __restrict__ invdeg,
                            int* __restrict__ cnt) {
    int i = blockIdx.x * blockDim.x + threadIdx.x;
    if (i < NN) {
        invdeg[i] = 1.0f / degree[i];
        cnt[i] = 0;
    }
}

// ---------------- CSR build ----------------
__global__ void hist_kernel(const int* __restrict__ dst, int* __restrict__ cnt,
                            int* __restrict__ rank) {
    int e = blockIdx.x * blockDim.x + threadIdx.x;
    if (e < EE) rank[e] = atomicAdd(&cnt[dst[e]], 1);
}

__global__ void scan1_kernel(const int* __restrict__ cnt, int* __restrict__ rowptr,
                             int* __restrict__ bsum) {
    __shared__ int ws[8];
    int tid = threadIdx.x, lane = tid & 31, wid = tid >> 5;
    int i = blockIdx.x * 256 + tid;
    int v = (i < NN) ? cnt[i] : 0;
    int x = v;
#pragma unroll
    for (int off = 1; off < 32; off <<= 1) {
        int y = __shfl_up_sync(0xffffffffu, x, off);
        if (lane >= off) x += y;
    }
    if (lane == 31) ws[wid] = x;
    __syncthreads();
    if (wid == 0 && lane < 8) {
        int s = ws[lane];
#pragma unroll
        for (int off = 1; off < 8; off <<= 1) {
            int y = __shfl_up_sync(0x000000ffu, s, off);
            if (lane >= off) s += y;
        }
        ws[lane] = s;
    }
    __syncthreads();
    int woff = wid ? ws[wid - 1] : 0;
    if (i < NN) rowptr[i] = woff + x - v;
    if (tid == 255) bsum[blockIdx.x] = woff + x;
}

__global__ void scan2_kernel(const int* __restrict__ bsum, int* __restrict__ boff,
                             int* __restrict__ rowptr) {
    __shared__ int ws[8];
    int tid = threadIdx.x, lane = tid & 31, wid = tid >> 5;
    int v = (tid < NBLK) ? bsum[tid] : 0;
    int x = v;
#pragma unroll
    for (int off = 1; off < 32; off <<= 1) {
        int y = __shfl_up_sync(0xffffffffu, x, off);
        if (lane >= off) x += y;
    }
    if (lane == 31) ws[wid] = x;
    __syncthreads();
    if (wid == 0 && lane < 8) {
        int s = ws[lane];
#pragma unroll
        for (int off = 1; off < 8; off <<= 1) {
            int y = __shfl_up_sync(0x000000ffu, s, off);
            if (lane >= off) s += y;
        }
        ws[lane] = s;
    }
    __syncthreads();
    int woff = wid ? ws[wid - 1] : 0;
    if (tid < NBLK) boff[tid] = woff + x - v;
    if (tid == 255) rowptr[NN] = woff + x;
}

__global__ void scan3_kernel(int* __restrict__ rowptr, const int* __restrict__ boff) {
    int i = blockIdx.x * 256 + threadIdx.x;
    if (i < NN) rowptr[i] += boff[blockIdx.x];
}

__global__ void fill_kernel(const int* __restrict__ src, const int* __restrict__ dst,
                            const int* __restrict__ rowptr, const int* __restrict__ rank,
                            int* __restrict__ col) {
    int e = blockIdx.x * blockDim.x + threadIdx.x;
    if (e >= EE) return;
    col[rowptr[dst[e]] + rank[e]] = src[e];
}

// ---------------- gather (fp8 messages) ----------------
// ADDBASE: acc starts from fp32 base row. OUTFP8: also write out8 = fp8(acc*invdeg).
template <bool ADDBASE, bool OUTFP8>
__global__ __launch_bounds__(256)
void gather_kernel(const unsigned char* __restrict__ msg, const float* __restrict__ base,
                   float* __restrict__ out, unsigned char* __restrict__ out8,
                   const float* __restrict__ invdeg,
                   const int* __restrict__ rowptr, const int* __restrict__ col) {
    int node = (blockIdx.x * blockDim.x + threadIdx.x) >> 5;
    int lane = threadIdx.x & 31;
    if (node >= NN) return;
    int s0 = __ldg(rowptr + node), s1 = __ldg(rowptr + node + 1);

    float4 acc;
    if (ADDBASE)
        acc = *reinterpret_cast<const float4*>(base + (size_t)node * HH + lane * 4);
    else
        acc = make_float4(0.f, 0.f, 0.f, 0.f);

    const unsigned char* mbase = msg + lane * 4;
    int e = s0;
    for (; e + 3 < s1; e += 4) {
        int u0 = __ldg(col + e),     u1 = __ldg(col + e + 1);
        int u2 = __ldg(col + e + 2), u3 = __ldg(col + e + 3);
        acc_fp8row(acc, mbase + (size_t)u0 * HH);
        acc_fp8row(acc, mbase + (size_t)u1 * HH);
        acc_fp8row(acc, mbase + (size_t)u2 * HH);
        acc_fp8row(acc, mbase + (size_t)u3 * HH);
    }
    for (; e < s1; e++) {
        int u0 = __ldg(col + e);
        acc_fp8row(acc, mbase + (size_t)u0 * HH);
    }

    *reinterpret_cast<float4*>(out + (size_t)node * HH + lane * 4) = acc;
    if (OUTFP8) {
        float iv = __ldg(invdeg + node);
        unsigned packed = (unsigned)packfp8x2(acc.x * iv, acc.y * iv)
                        | ((unsigned)packfp8x2(acc.z * iv, acc.w * iv) << 16);
        *reinterpret_cast<unsigned*>(out8 + (size_t)node * HH + lane * 4) = packed;
    }
}

// ---------------- tf32 tensor-core GEMM ----------------
// OUTMODE: 0 = colsum only; 1 = fp8 unscaled to C8; 2 = fp32 to C + fp8*invdeg to C8.
template <int K, bool LEAKY, int OUTMODE>
__global__ __launch_bounds__(256, 2)
void gemm_tc(const float* __restrict__ A, const float* __restrict__ W,
             const float* __restrict__ bias, float* __restrict__ C,
             unsigned char* __restrict__ C8, const float* __restrict__ invdeg,
             float* __restrict__ colsum, int cs_off) {
    __shared__ unsigned As[128][36];
    __shared__ unsigned Ws[32][132];
    __shared__ float colsm[HH];

    const int tid = threadIdx.x;
    const int warp = tid >> 5, lane = tid & 31;
    const int wm = warp & 3, wn = warp >> 2;
    const int g = lane >> 2, t = lane & 3;
    const int row0 = blockIdx.x * 128;

    float acc[2][8][4];
#pragma unroll
    for (int mt = 0; mt < 2; mt++)
#pragma unroll
        for (int nt = 0; nt < 8; nt++)
#pragma unroll
            for (int r = 0; r < 4; r++) acc[mt][nt][r] = 0.f;

    if (tid < HH) colsm[tid] = 0.f;

    for (int k0 = 0; k0 < K; k0 += 32) {
#pragma unroll
        for (int i = 0; i < 4; i++) {
            int idx = tid + i * 256;
            int r = idx >> 3, q = idx & 7;
            float4 v = make_float4(0.f, 0.f, 0.f, 0.f);
            if (row0 + r < NN)
                v = *reinterpret_cast<const float4*>(A + (size_t)(row0 + r) * K + k0 + q * 4);
            unsigned* p = &As[r][q * 4];
            p[0] = f2tf32(v.x); p[1] = f2tf32(v.y); p[2] = f2tf32(v.z); p[3] = f2tf32(v.w);
        }
#pragma unroll
        for (int i = 0; i < 4; i++) {
            int idx = tid + i * 256;
            int kk = idx >> 5, n4 = idx & 31;
            float4 w = *reinterpret_cast<const float4*>(W + (size_t)(k0 + kk) * HH + n4 * 4);
            unsigned* p = &Ws[kk][n4 * 4];
            p[0] = f2tf32(w.x); p[1] = f2tf32(w.y); p[2] = f2tf32(w.z); p[3] = f2tf32(w.w);
        }
        __syncthreads();

#pragma unroll
        for (int k8 = 0; k8 < 4; k8++) {
            const int kk = k8 * 8;
            unsigned a[2][4], b[8][2];
#pragma unroll
            for (int mt = 0; mt < 2; mt++) {
                int r = wm * 32 + mt * 16;
                a[mt][0] = As[r + g][kk + t];
                a[mt][1] = As[r + g + 8][kk + t];
                a[mt][2] = As[r + g][kk + t + 4];
                a[mt][3] = As[r + g + 8][kk + t + 4];
            }
#pragma unroll
            for (int nt = 0; nt < 8; nt++) {
                int n = wn * 64 + nt * 8;
                b[nt][0] = Ws[kk + t][n + g];
                b[nt][1] = Ws[kk + t + 4][n + g];
            }
#pragma unroll
            for (int mt = 0; mt < 2; mt++)
#pragma unroll
                for (int nt = 0; nt < 8; nt++)
                    mma_tf32(acc[mt][nt], a[mt], b[nt]);
        }
        __syncthreads();
    }

    float csum[8][2];
#pragma unroll
    for (int nt = 0; nt < 8; nt++) { csum[nt][0] = 0.f; csum[nt][1] = 0.f; }

#pragma unroll
    for (int mt = 0; mt < 2; mt++) {
        int rr[2];
        rr[0] = row0 + wm * 32 + mt * 16 + g;
        rr[1] = rr[0] + 8;
#pragma unroll
        for (int half = 0; half < 2; half++) {
            int r = rr[half];
            if (r >= NN) continue;
            float iv = (OUTMODE == 2) ? __ldg(invdeg + r) : 1.0f;
#pragma unroll
            for (int nt = 0; nt < 8; nt++) {
                int col = wn * 64 + nt * 8 + 2 * t;
                float b0 = __ldg(bias + col), b1 = __ldg(bias + col + 1);
                float x0 = acc[mt][nt][half * 2 + 0] + b0;
                float x1 = acc[mt][nt][half * 2 + 1] + b1;
                if (LEAKY) {
                    x0 = (x0 >= 0.f) ? x0 : NEG_SLOPE * x0;
                    x1 = (x1 >= 0.f) ? x1 : NEG_SLOPE * x1;
                }
                csum[nt][0] += x0; csum[nt][1] += x1;
                if (OUTMODE == 2)
                    *reinterpret_cast<float2*>(C + (size_t)r * HH + col) = make_float2(x0, x1);
                if (OUTMODE == 1 || OUTMODE == 2) {
                    *reinterpret_cast<unsigned short*>(C8 + (size_t)r * HH + col) =
                        packfp8x2(x0 * iv, x1 * iv);
                }
            }
        }
    }

    __syncthreads();
#pragma unroll
    for (int nt = 0; nt < 8; nt++) {
#pragma unroll
        for (int c = 0; c < 2; c++) {
            float s = csum[nt][c];
            s += __shfl_xor_sync(0xffffffffu, s, 4);
            s += __shfl_xor_sync(0xffffffffu, s, 8);
            s += __shfl_xor_sync(0xffffffffu, s, 16);
            if (g == 0) atomicAdd(&colsm[wn * 64 + nt * 8 + 2 * t + c], s);
        }
    }
    __syncthreads();
    if (tid < HH) atomicAdd(&colsum[cs_off + tid], colsm[tid]);
}

// ---------------- final ----------------
__global__ void final_kernel(const float* __restrict__ colsum,
                             const float* __restrict__ Wpred, const float* __restrict__ bpred,
                             const float* __restrict__ Wcls, const float* __restrict__ bcls,
                             float* __restrict__ out) {
    __shared__ float cm[HH * (LL + 1)];
    __shared__ float gsh[HH];
    int tid = threadIdx.x;  // 128 threads
    for (int t = tid; t < HH * (LL + 1); t += 128) cm[t] = colsum[t] * (1.0f / (float)NN);
    __syncthreads();
    float g = bpred[tid];
    for (int k = 0; k < HH * (LL + 1); k++) g += cm[k] * Wpred[(size_t)k * HH + tid];
    gsh[tid] = g;
    __syncthreads();
    if (tid == 0) {
        float l0 = bcls[0], l1 = bcls[1];
        for (int j = 0; j < HH; j++) {
            l0 += gsh[j] * Wcls[j * 2 + 0];
            l1 += gsh[j] * Wcls[j * 2 + 1];
        }
        float m = fmaxf(l0, l1);
        float e0 = expf(l0 - m), e1 = expf(l1 - m);
        float inv = 1.0f / (e0 + e1);
        out[0] = e0 * inv;
        out[1] = e1 * inv;
    }
}

// ---------------- launch ----------------
extern "C" void kernel_launch(void* const* d_in, const int* in_sizes, int n_in,
                              void* d_out, int out_size) {
    const float* node_feat = (const float*)d_in[0];
    const float* degree    = (const float*)d_in[3];
    const float* Wn        = (const float*)d_in[4];
    const float* bn        = (const float*)d_in[5];
    const float* Wgcn      = (const float*)d_in[8];
    const float* bgcn      = (const float*)d_in[9];
    const float* Wpred     = (const float*)d_in[10];
    const float* bpred     = (const float*)d_in[11];
    const float* Wcls      = (const float*)d_in[12];
    const float* bcls      = (const float*)d_in[13];
    const int*   src       = (const int*)d_in[14];
    const int*   dst       = (const int*)d_in[15];
    float* out = (float*)d_out;

    float *p_cur, *p_agg, *p_inv, *p_cs;
    unsigned char *p_h08, *p_msg8;
    int *p_cnt, *p_rank, *p_rp, *p_col, *p_bsum, *p_boff;
    cudaGetSymbolAddress((void**)&p_cur,  g_cur);
    cudaGetSymbolAddress((void**)&p_agg,  g_agg);
    cudaGetSymbolAddress((void**)&p_h08,  g_h08);
    cudaGetSymbolAddress((void**)&p_msg8, g_msg8);
    cudaGetSymbolAddress((void**)&p_inv,  g_invdeg);
    cudaGetSymbolAddress((void**)&p_cs,   g_colsum);
    cudaGetSymbolAddress((void**)&p_cnt,  g_cnt);
    cudaGetSymbolAddress((void**)&p_rank, g_rank);
    cudaGetSymbolAddress((void**)&p_rp,   g_rowptr);
    cudaGetSymbolAddress((void**)&p_col,  g_col);
    cudaGetSymbolAddress((void**)&p_bsum, g_bsum);
    cudaGetSymbolAddress((void**)&p_boff, g_boff);

    const int gemm_blocks = (NN + 127) / 128;        // 391
    const int edge_blocks = (EE + 255) / 256;        // 3125
    const int node_blocks = NBLK;                    // 196
    const int gath_blocks = (NN * 32 + 255) / 256;   // 6250

    // side stream + fork/join events (host objects, created once; no device alloc)
    static cudaStream_t s2 = nullptr;
    static cudaEvent_t evFork = nullptr, evJoin = nullptr;
    if (s2 == nullptr) {
        cudaStreamCreateWithFlags(&s2, cudaStreamNonBlocking);
        cudaEventCreateWithFlags(&evFork, cudaEventDisableTiming);
        cudaEventCreateWithFlags(&evJoin, cudaEventDisableTiming);
    }

    // 0) zero colsum on the MAIN stream (proj GEMM epilogue accumulates into it)
    zero_cs_kernel<<<2, 256>>>(p_cs);

    // ---- fork ----
    cudaEventRecord(evFork, 0);
    cudaStreamWaitEvent(s2, evFork, 0);

    // s2 leg: invdeg + CSR build
    init_kernel<<<node_blocks, 256, 0, s2>>>(degree, p_inv, p_cnt);
    hist_kernel<<<edge_blocks, 256, 0, s2>>>(dst, p_cnt, p_rank);
    scan1_kernel<<<node_blocks, 256, 0, s2>>>(p_cnt, p_rp, p_bsum);
    scan2_kernel<<<1, 256, 0, s2>>>(p_bsum, p_boff, p_rp);
    scan3_kernel<<<node_blocks, 256, 0, s2>>>(p_rp, p_boff);
    fill_kernel<<<edge_blocks, 256, 0, s2>>>(src, dst, p_rp, p_rank, p_col);
    cudaEventRecord(evJoin, s2);

    // main leg: projection GEMM (independent of CSR): h08 = fp8(A@Wn+bn), colsum[0:128]
    gemm_tc<NF, false, 1><<<gemm_blocks, 256>>>(node_feat, Wn, bn, nullptr, p_h08,
                                                nullptr, p_cs, 0);

    // ---- join: fusion gather needs CSR + invdeg (s2) and h08 (main) ----
    cudaStreamWaitEvent(0, evJoin, 0);

    // fusion: cur[v] = sum_{u->v} h08[u] ; msg8[v] = fp8(cur[v]*invdeg[v])
    gather_kernel<false, true><<<gath_blocks, 256>>>(p_h08, nullptr, p_cur, p_msg8,
                                                     p_inv, p_rp, p_col);

    // 3 GCN layers
    for (int l = 0; l < LL; l++) {
        gather_kernel<true, false><<<gath_blocks, 256>>>(p_msg8, p_cur, p_agg, nullptr,
                                                         nullptr, p_rp, p_col);
        if (l < LL - 1)
            gemm_tc<HH, true, 2><<<gemm_blocks, 256>>>(p_agg, Wgcn, bgcn, p_cur, p_msg8,
                                                       p_inv, p_cs, (l + 1) * HH);
        else
            gemm_tc<HH, true, 0><<<gemm_blocks, 256>>>(p_agg, Wgcn, bgcn, nullptr, nullptr,
                                                       nullptr, p_cs, (l + 1) * HH);
    }

    // readout
    final_kernel<<<1, 128>>>(p_cs, Wpred, bpred, Wcls, bcls, out);
}